// round 1
// baseline (speedup 1.0000x reference)
#include <cuda_runtime.h>
#include <cstdint>

// Problem constants (shapes fixed by the dataset)
#define HID 768
#define MAXK 64
#define NMENT 4096

// Tiling
#define BM 128
#define BN 64
#define BK 32
#define SA_STRIDE 36              // 36 % 32 == 4 -> bank = 4*gid + tg (conflict-free)
#define SB_STRIDE 72              // 72 % 32 == 8 -> bank = 8*tg + gid (conflict-free)
#define ASZ (BM * SA_STRIDE)      // 4608 floats / stage
#define BSZ (BK * SB_STRIDE)      // 2304 floats / stage
#define SMEM_FLOATS (2 * ASZ + 2 * BSZ)
#define SMEM_BYTES (SMEM_FLOATS * 4)   // 55296 B

// Scratch for Mpart = mention_embs @ W1_top + b1  (12.6 MB device global, no alloc)
__device__ float g_Mpart[NMENT * HID];

__device__ __forceinline__ void cp_async16(float* sptr, const float* gptr) {
    uint32_t s = (uint32_t)__cvta_generic_to_shared(sptr);
    asm volatile("cp.async.cg.shared.global [%0], [%1], 16;\n" :: "r"(s), "l"(gptr));
}
__device__ __forceinline__ void cp_commit() { asm volatile("cp.async.commit_group;\n"); }
template <int W_>
__device__ __forceinline__ void cp_wait() { asm volatile("cp.async.wait_group %0;\n" :: "n"(W_)); }

__device__ __forceinline__ void mma_tf32(float& c0, float& c1, float& c2, float& c3,
                                         uint32_t a0, uint32_t a1, uint32_t a2, uint32_t a3,
                                         uint32_t b0, uint32_t b1) {
    asm volatile(
        "mma.sync.aligned.m16n8k8.row.col.f32.tf32.tf32.f32 "
        "{%0,%1,%2,%3}, {%4,%5,%6,%7}, {%8,%9}, {%0,%1,%2,%3};\n"
        : "+f"(c0), "+f"(c1), "+f"(c2), "+f"(c3)
        : "r"(a0), "r"(a1), "r"(a2), "r"(a3), "r"(b0), "r"(b1));
}

// Output init: out[n,k] = 0.5*prior[n,k] for k<64, out[n,64] = nota_bias.
__global__ void init_out_kernel(float* __restrict__ out, const float* __restrict__ prior,
                                const float* __restrict__ nota, int n) {
    int i = blockIdx.x * blockDim.x + threadIdx.x;
    int total = n * (MAXK + 1);
    if (i < total) {
        int k = i % (MAXK + 1);
        int row = i / (MAXK + 1);
        out[i] = (k < MAXK) ? 0.5f * prior[row * MAXK + k] : nota[0];
    }
}

// Unified tiled TF32 GEMM.
// MAIN=false: Mpart = A @ B + b1              (A = mention_embs, B = W1_top)
// MAIN=true : fused cand GEMM + relu + W2 dot + scatter-atomicAdd into out
//             (A = candidate_embs, B = W1_bot)
template <bool MAIN>
__global__ __launch_bounds__(256)
void gemm_kernel(const float* __restrict__ A, const float* __restrict__ B,
                 const float* __restrict__ b1, const float* __restrict__ W2,
                 const float* __restrict__ b2v,
                 const int* __restrict__ midx, const int* __restrict__ cidx,
                 float* __restrict__ out) {
    extern __shared__ float smem[];
    float* sAbase = smem;                 // 2 stages of A
    float* sBbase = smem + 2 * ASZ;       // 2 stages of B

    const int tid   = threadIdx.x;
    const int warp  = tid >> 5;
    const int lane  = tid & 31;
    const int warpM = warp >> 1;          // 0..3 (M direction, 32 rows each)
    const int warpN = warp & 1;           // 0..1 (N direction, 32 cols each)
    const int gid   = lane >> 2;          // 0..7
    const int tg    = lane & 3;           // 0..3

    const float* Ablk = A + (size_t)blockIdx.y * BM * HID;
    const float* Bblk = B + blockIdx.x * BN;

    float c[2][4][4];
#pragma unroll
    for (int mi = 0; mi < 2; ++mi)
#pragma unroll
        for (int ni = 0; ni < 4; ++ni)
#pragma unroll
            for (int j = 0; j < 4; ++j) c[mi][ni][j] = 0.f;

    auto load_tiles = [&](int kt, int stage) {
        float* sa = sAbase + stage * ASZ;
        float* sb = sBbase + stage * BSZ;
#pragma unroll
        for (int i = 0; i < 4; ++i) {                  // 128x32 A tile: 1024 float4
            int idx = tid + i * 256;
            int r = idx >> 3, c4 = (idx & 7) << 2;
            cp_async16(sa + r * SA_STRIDE + c4, Ablk + (size_t)r * HID + kt * BK + c4);
        }
#pragma unroll
        for (int i = 0; i < 2; ++i) {                  // 32x64 B tile: 512 float4
            int idx = tid + i * 256;
            int kr = idx >> 4, c4 = (idx & 15) << 2;
            cp_async16(sb + kr * SB_STRIDE + c4, Bblk + (size_t)(kt * BK + kr) * HID + c4);
        }
    };

    load_tiles(0, 0);
    cp_commit();

    const int NK = HID / BK;  // 24
    for (int kt = 0; kt < NK; ++kt) {
        const int stage = kt & 1;
        if (kt + 1 < NK) {
            load_tiles(kt + 1, stage ^ 1);
            cp_commit();
            cp_wait<1>();
        } else {
            cp_wait<0>();
        }
        __syncthreads();

        const float* sa = sAbase + stage * ASZ;
        const float* sb = sBbase + stage * BSZ;
#pragma unroll
        for (int ks = 0; ks < 4; ++ks) {
            const int k = ks * 8;
            uint32_t a[2][4], b[4][2];
#pragma unroll
            for (int mi = 0; mi < 2; ++mi) {
                const int r = warpM * 32 + mi * 16 + gid;
                a[mi][0] = __float_as_uint(sa[r * SA_STRIDE + k + tg]);
                a[mi][1] = __float_as_uint(sa[(r + 8) * SA_STRIDE + k + tg]);
                a[mi][2] = __float_as_uint(sa[r * SA_STRIDE + k + tg + 4]);
                a[mi][3] = __float_as_uint(sa[(r + 8) * SA_STRIDE + k + tg + 4]);
            }
#pragma unroll
            for (int ni = 0; ni < 4; ++ni) {
                const int col = warpN * 32 + ni * 8 + gid;
                b[ni][0] = __float_as_uint(sb[(k + tg) * SB_STRIDE + col]);
                b[ni][1] = __float_as_uint(sb[(k + tg + 4) * SB_STRIDE + col]);
            }
#pragma unroll
            for (int mi = 0; mi < 2; ++mi)
#pragma unroll
                for (int ni = 0; ni < 4; ++ni)
                    mma_tf32(c[mi][ni][0], c[mi][ni][1], c[mi][ni][2], c[mi][ni][3],
                             a[mi][0], a[mi][1], a[mi][2], a[mi][3],
                             b[ni][0], b[ni][1]);
        }
        __syncthreads();
    }

    const int rowBase = blockIdx.y * BM + warpM * 32;
    const int colBase = blockIdx.x * BN + warpN * 32;

    if (MAIN) {
        // Fused epilogue: h = relu(c + Mpart[midx[row], col]); partial = sum(h * W2[col]);
        // reduce over the 4 lanes covering this warp's 32 cols; scatter-add.
        float w2v[8];
#pragma unroll
        for (int ni = 0; ni < 4; ++ni) {
            w2v[ni * 2]     = __ldg(W2 + colBase + ni * 8 + tg * 2);
            w2v[ni * 2 + 1] = __ldg(W2 + colBase + ni * 8 + tg * 2 + 1);
        }
#pragma unroll
        for (int mi = 0; mi < 2; ++mi)
#pragma unroll
            for (int rr = 0; rr < 2; ++rr) {
                const int prow = rowBase + mi * 16 + rr * 8 + gid;
                const int m = __ldg(midx + prow);
                const float* mp = g_Mpart + (size_t)m * HID;
                float acc = 0.f;
#pragma unroll
                for (int ni = 0; ni < 4; ++ni)
#pragma unroll
                    for (int cc2 = 0; cc2 < 2; ++cc2) {
                        const int col = colBase + ni * 8 + tg * 2 + cc2;
                        float v = c[mi][ni][rr * 2 + cc2] + __ldg(mp + col);
                        acc = fmaf(fmaxf(v, 0.f), w2v[ni * 2 + cc2], acc);
                    }
                acc += __shfl_xor_sync(0xffffffffu, acc, 1);
                acc += __shfl_xor_sync(0xffffffffu, acc, 2);
                if (tg == 0) {
                    if (blockIdx.x == 0 && warpN == 0) acc += __ldg(b2v);  // b2 once per pair
                    atomicAdd(out + (size_t)m * (MAXK + 1) + __ldg(cidx + prow), acc);
                }
            }
    } else {
        // Mpart epilogue: write c + b1 to scratch.
#pragma unroll
        for (int mi = 0; mi < 2; ++mi)
#pragma unroll
            for (int rr = 0; rr < 2; ++rr) {
                const int row = rowBase + mi * 16 + rr * 8 + gid;
#pragma unroll
                for (int ni = 0; ni < 4; ++ni) {
                    const int col = colBase + ni * 8 + tg * 2;
                    float2 v;
                    v.x = c[mi][ni][rr * 2]     + __ldg(b1 + col);
                    v.y = c[mi][ni][rr * 2 + 1] + __ldg(b1 + col + 1);
                    *reinterpret_cast<float2*>(&g_Mpart[(size_t)row * HID + col]) = v;
                }
            }
    }
}

extern "C" void kernel_launch(void* const* d_in, const int* in_sizes, int n_in,
                              void* d_out, int out_size) {
    const float* mention = (const float*)d_in[0];  // [N, 768]
    const float* cand    = (const float*)d_in[1];  // [T, 768]
    const float* W1      = (const float*)d_in[2];  // [1536, 768]
    const float* b1      = (const float*)d_in[3];  // [768]
    const float* W2      = (const float*)d_in[4];  // [768, 1]
    const float* b2      = (const float*)d_in[5];  // [1]
    const float* prior   = (const float*)d_in[6];  // [N, 64]
    const float* nota    = (const float*)d_in[7];  // []
    const int*   midx    = (const int*)d_in[8];    // [T]
    const int*   cidx    = (const int*)d_in[9];    // [T]
    float* out = (float*)d_out;                    // [N, 65]

    const int N = in_sizes[0] / HID;   // 4096
    const int T = in_sizes[1] / HID;   // 131072

    cudaFuncSetAttribute(gemm_kernel<false>, cudaFuncAttributeMaxDynamicSharedMemorySize, SMEM_BYTES);
    cudaFuncSetAttribute(gemm_kernel<true>,  cudaFuncAttributeMaxDynamicSharedMemorySize, SMEM_BYTES);

    // 1) out = 0.5*prior  (+ nota col)
    init_out_kernel<<<(N * (MAXK + 1) + 255) / 256, 256>>>(out, prior, nota, N);

    // 2) Mpart = mention_embs @ W1_top + b1
    gemm_kernel<false><<<dim3(HID / BN, N / BM), 256, SMEM_BYTES>>>(
        mention, W1, b1, W2, b2, nullptr, nullptr, out);

    // 3) fused: cand @ W1_bot -> +Mpart -> relu -> @W2 (+b2) -> scatter-add into out
    gemm_kernel<true><<<dim3(HID / BN, T / BM), 256, SMEM_BYTES>>>(
        cand, W1 + (size_t)HID * HID, b1, W2, b2, midx, cidx, out);
}

// round 2
// speedup vs baseline: 1.0341x; 1.0341x over previous
#include <cuda_runtime.h>
#include <cstdint>

// Problem constants (shapes fixed by the dataset)
#define HID 768
#define MAXK 64
#define NMENT 4096

// Tiling
#define BM 256
#define BN 128
#define BK 32
#define NSTAGE 3
#define SA_STRIDE 36               // bank = 4*gid + tg  (conflict-free A reads)
#define SB_STRIDE 136              // bank = 8*tg + gid  (conflict-free B reads)
#define ASZ (BM * SA_STRIDE)       // 9216 floats / stage
#define BSZ (BK * SB_STRIDE)       // 4352 floats / stage
#define STAGE_FLOATS (ASZ + BSZ)
#define SMEM_BYTES (NSTAGE * STAGE_FLOATS * 4)   // 162816 B

// Scratch for Mpart = mention_embs @ W1_top + b1
__device__ float g_Mpart[NMENT * HID];

__device__ __forceinline__ void cp_async16(float* sptr, const float* gptr) {
    uint32_t s = (uint32_t)__cvta_generic_to_shared(sptr);
    asm volatile("cp.async.cg.shared.global [%0], [%1], 16;\n" :: "r"(s), "l"(gptr));
}
__device__ __forceinline__ void cp_commit() { asm volatile("cp.async.commit_group;\n"); }
template <int W_>
__device__ __forceinline__ void cp_wait() { asm volatile("cp.async.wait_group %0;\n" :: "n"(W_)); }

__device__ __forceinline__ void mma_tf32(float& c0, float& c1, float& c2, float& c3,
                                         uint32_t a0, uint32_t a1, uint32_t a2, uint32_t a3,
                                         uint32_t b0, uint32_t b1) {
    asm volatile(
        "mma.sync.aligned.m16n8k8.row.col.f32.tf32.tf32.f32 "
        "{%0,%1,%2,%3}, {%4,%5,%6,%7}, {%8,%9}, {%0,%1,%2,%3};\n"
        : "+f"(c0), "+f"(c1), "+f"(c2), "+f"(c3)
        : "r"(a0), "r"(a1), "r"(a2), "r"(a3), "r"(b0), "r"(b1));
}

__global__ void init_out_kernel(float* __restrict__ out, const float* __restrict__ prior,
                                const float* __restrict__ nota, int n) {
    int i = blockIdx.x * blockDim.x + threadIdx.x;
    int total = n * (MAXK + 1);
    if (i < total) {
        int k = i % (MAXK + 1);
        int row = i / (MAXK + 1);
        out[i] = (k < MAXK) ? 0.5f * prior[row * MAXK + k] : nota[0];
    }
}

// Unified tiled TF32 GEMM, BM=256 x BN=128, warp tile 64x64 (mi=4, ni=8).
// MAIN=false: g_Mpart = A @ B + b1
// MAIN=true : fused cand GEMM + Mpart gather + relu + W2 dot + scatter-atomicAdd
template <bool MAIN>
__global__ __launch_bounds__(256, 1)
void gemm_kernel(const float* __restrict__ A, const float* __restrict__ B,
                 const float* __restrict__ b1, const float* __restrict__ W2,
                 const float* __restrict__ b2v,
                 const int* __restrict__ midx, const int* __restrict__ cidx,
                 float* __restrict__ out) {
    extern __shared__ float smem[];

    const int tid   = threadIdx.x;
    const int warp  = tid >> 5;
    const int lane  = tid & 31;
    const int warpM = warp >> 1;          // 0..3  (64 rows each)
    const int warpN = warp & 1;           // 0..1  (64 cols each)
    const int gid   = lane >> 2;          // 0..7
    const int tg    = lane & 3;           // 0..3

    const float* Ablk = A + (size_t)blockIdx.y * BM * HID;
    const float* Bblk = B + blockIdx.x * BN;

    float c[4][8][4];
#pragma unroll
    for (int mi = 0; mi < 4; ++mi)
#pragma unroll
        for (int ni = 0; ni < 8; ++ni)
#pragma unroll
            for (int j = 0; j < 4; ++j) c[mi][ni][j] = 0.f;

    auto load_tiles = [&](int kt, int stage) {
        float* sa = smem + stage * STAGE_FLOATS;
        float* sb = sa + ASZ;
#pragma unroll
        for (int i = 0; i < 8; ++i) {                  // 256x32 A tile: 2048 float4
            int idx = tid + i * 256;
            int r = idx >> 3, c4 = (idx & 7) << 2;
            cp_async16(sa + r * SA_STRIDE + c4, Ablk + (size_t)r * HID + kt * BK + c4);
        }
#pragma unroll
        for (int i = 0; i < 4; ++i) {                  // 32x128 B tile: 1024 float4
            int idx = tid + i * 256;
            int kr = idx >> 5, c4 = (idx & 31) << 2;
            cp_async16(sb + kr * SB_STRIDE + c4, Bblk + (size_t)(kt * BK + kr) * HID + c4);
        }
    };

    load_tiles(0, 0); cp_commit();
    load_tiles(1, 1); cp_commit();

    const int NK = HID / BK;  // 24
    int stage = 0;
    for (int kt = 0; kt < NK; ++kt) {
        if (kt + 1 < NK) cp_wait<1>(); else cp_wait<0>();
        __syncthreads();
        if (kt + 2 < NK) {
            int ws = stage + 2; if (ws >= NSTAGE) ws -= NSTAGE;
            load_tiles(kt + 2, ws);
            cp_commit();
        }

        const float* sa = smem + stage * STAGE_FLOATS;
        const float* sb = sa + ASZ;
#pragma unroll
        for (int ks = 0; ks < 4; ++ks) {
            const int k = ks * 8;
            uint32_t a[4][4], b[8][2];
#pragma unroll
            for (int mi = 0; mi < 4; ++mi) {
                const int r = warpM * 64 + mi * 16 + gid;
                a[mi][0] = __float_as_uint(sa[r * SA_STRIDE + k + tg]);
                a[mi][1] = __float_as_uint(sa[(r + 8) * SA_STRIDE + k + tg]);
                a[mi][2] = __float_as_uint(sa[r * SA_STRIDE + k + tg + 4]);
                a[mi][3] = __float_as_uint(sa[(r + 8) * SA_STRIDE + k + tg + 4]);
            }
#pragma unroll
            for (int ni = 0; ni < 8; ++ni) {
                const int col = warpN * 64 + ni * 8 + gid;
                b[ni][0] = __float_as_uint(sb[(k + tg) * SB_STRIDE + col]);
                b[ni][1] = __float_as_uint(sb[(k + tg + 4) * SB_STRIDE + col]);
            }
#pragma unroll
            for (int mi = 0; mi < 4; ++mi)
#pragma unroll
                for (int ni = 0; ni < 8; ++ni)
                    mma_tf32(c[mi][ni][0], c[mi][ni][1], c[mi][ni][2], c[mi][ni][3],
                             a[mi][0], a[mi][1], a[mi][2], a[mi][3],
                             b[ni][0], b[ni][1]);
        }
        ++stage; if (stage >= NSTAGE) stage = 0;
    }

    const int rowBase = blockIdx.y * BM + warpM * 64;
    const int colBase = blockIdx.x * BN + warpN * 64;

    if (MAIN) {
        // h = relu(c + Mpart[midx[row], col]); partial = sum(h * W2[col]); scatter-add.
        float w2v[8][2];
#pragma unroll
        for (int ni = 0; ni < 8; ++ni) {
            w2v[ni][0] = __ldg(W2 + colBase + ni * 8 + tg * 2);
            w2v[ni][1] = __ldg(W2 + colBase + ni * 8 + tg * 2 + 1);
        }
#pragma unroll
        for (int mi = 0; mi < 4; ++mi)
#pragma unroll
            for (int rr = 0; rr < 2; ++rr) {
                const int prow = rowBase + mi * 16 + rr * 8 + gid;
                const int m = __ldg(midx + prow);
                const float* mp = g_Mpart + (size_t)m * HID;
                float acc = 0.f;
#pragma unroll
                for (int ni = 0; ni < 8; ++ni) {
                    const int col = colBase + ni * 8 + tg * 2;
                    float v0 = c[mi][ni][rr * 2]     + __ldg(mp + col);
                    float v1 = c[mi][ni][rr * 2 + 1] + __ldg(mp + col + 1);
                    acc = fmaf(fmaxf(v0, 0.f), w2v[ni][0], acc);
                    acc = fmaf(fmaxf(v1, 0.f), w2v[ni][1], acc);
                }
                acc += __shfl_xor_sync(0xffffffffu, acc, 1);
                acc += __shfl_xor_sync(0xffffffffu, acc, 2);
                if (tg == 0) {
                    if (blockIdx.x == 0 && warpN == 0) acc += __ldg(b2v);
                    atomicAdd(out + (size_t)m * (MAXK + 1) + __ldg(cidx + prow), acc);
                }
            }
    } else {
        // Mpart epilogue: write c + b1 to scratch.
#pragma unroll
        for (int mi = 0; mi < 4; ++mi)
#pragma unroll
            for (int rr = 0; rr < 2; ++rr) {
                const int row = rowBase + mi * 16 + rr * 8 + gid;
#pragma unroll
                for (int ni = 0; ni < 8; ++ni) {
                    const int col = colBase + ni * 8 + tg * 2;
                    float2 v;
                    v.x = c[mi][ni][rr * 2]     + __ldg(b1 + col);
                    v.y = c[mi][ni][rr * 2 + 1] + __ldg(b1 + col + 1);
                    *reinterpret_cast<float2*>(&g_Mpart[(size_t)row * HID + col]) = v;
                }
            }
    }
}

extern "C" void kernel_launch(void* const* d_in, const int* in_sizes, int n_in,
                              void* d_out, int out_size) {
    const float* mention = (const float*)d_in[0];  // [N, 768]
    const float* cand    = (const float*)d_in[1];  // [T, 768]
    const float* W1      = (const float*)d_in[2];  // [1536, 768]
    const float* b1      = (const float*)d_in[3];  // [768]
    const float* W2      = (const float*)d_in[4];  // [768, 1]
    const float* b2      = (const float*)d_in[5];  // [1]
    const float* prior   = (const float*)d_in[6];  // [N, 64]
    const float* nota    = (const float*)d_in[7];  // []
    const int*   midx    = (const int*)d_in[8];    // [T]
    const int*   cidx    = (const int*)d_in[9];    // [T]
    float* out = (float*)d_out;                    // [N, 65]

    const int N = in_sizes[0] / HID;   // 4096
    const int T = in_sizes[1] / HID;   // 131072

    cudaFuncSetAttribute(gemm_kernel<false>, cudaFuncAttributeMaxDynamicSharedMemorySize, SMEM_BYTES);
    cudaFuncSetAttribute(gemm_kernel<true>,  cudaFuncAttributeMaxDynamicSharedMemorySize, SMEM_BYTES);

    // 1) out = 0.5*prior (+ nota col)
    init_out_kernel<<<(N * (MAXK + 1) + 255) / 256, 256>>>(out, prior, nota, N);

    // 2) Mpart = mention_embs @ W1_top + b1
    gemm_kernel<false><<<dim3(HID / BN, N / BM), 256, SMEM_BYTES>>>(
        mention, W1, b1, W2, b2, nullptr, nullptr, out);

    // 3) fused: cand @ W1_bot -> +Mpart -> relu -> @W2 (+b2) -> scatter-add into out
    gemm_kernel<true><<<dim3(HID / BN, T / BM), 256, SMEM_BYTES>>>(
        cand, W1 + (size_t)HID * HID, b1, W2, b2, midx, cidx, out);
}

// round 4
// speedup vs baseline: 1.3290x; 1.2852x over previous
#include <cuda_runtime.h>
#include <cuda_fp16.h>
#include <cstdint>

// ---------------- problem constants ----------------
#define HID 768
#define W1ROWS 1536
#define MAXK 64
#define NMENT 4096
#define TPAIR 131072

// ---------------- tiling ----------------
#define BM 128
#define BN 256
#define BK 32                        // 32 halves per k-tile (2 mma k-steps of 16)
#define NKT (HID / BK)               // 24
#define SROW 40                      // smem row stride in halves (20 half2) -> conflict-free
#define A_STAGE_H (BM * SROW)        // 5120 halves
#define B_STAGE_H (BN * SROW)        // 10240 halves
#define STAGE_H (A_STAGE_H + B_STAGE_H)
#define NSTAGE 3
#define SMEM_BYTES (NSTAGE * STAGE_H * 2)   // 92160 B

// ---------------- device scratch (static, no allocs) ----------------
__device__ float  g_Mpart[NMENT * HID];        // mention @ W1_top + b1 (fp32)
__device__ __half g_W1TH[HID * W1ROWS];        // W1 transposed -> [n][k] fp16
__device__ __half g_candH[(size_t)TPAIR * HID];
__device__ __half g_mentH[NMENT * HID];

// ---------------- helpers ----------------
__device__ __forceinline__ void cp_async16(void* sptr, const void* gptr) {
    uint32_t s = (uint32_t)__cvta_generic_to_shared(sptr);
    asm volatile("cp.async.cg.shared.global [%0], [%1], 16;\n" :: "r"(s), "l"(gptr));
}
__device__ __forceinline__ void cp_commit() { asm volatile("cp.async.commit_group;\n"); }
template <int W_>
__device__ __forceinline__ void cp_wait() { asm volatile("cp.async.wait_group %0;\n" :: "n"(W_)); }

__device__ __forceinline__ void mma_f16(float& c0, float& c1, float& c2, float& c3,
                                        uint32_t a0, uint32_t a1, uint32_t a2, uint32_t a3,
                                        uint32_t b0, uint32_t b1) {
    asm volatile(
        "mma.sync.aligned.m16n8k16.row.col.f32.f16.f16.f32 "
        "{%0,%1,%2,%3}, {%4,%5,%6,%7}, {%8,%9}, {%0,%1,%2,%3};\n"
        : "+f"(c0), "+f"(c1), "+f"(c2), "+f"(c3)
        : "r"(a0), "r"(a1), "r"(a2), "r"(a3), "r"(b0), "r"(b1));
}

// ---------------- aux kernels ----------------
__global__ void init_out_kernel(float* __restrict__ out, const float* __restrict__ prior,
                                const float* __restrict__ nota, int n) {
    int i = blockIdx.x * blockDim.x + threadIdx.x;
    if (i < n * (MAXK + 1)) {
        int k = i % (MAXK + 1);
        int row = i / (MAXK + 1);
        out[i] = (k < MAXK) ? 0.5f * prior[row * MAXK + k] : nota[0];
    }
}

// fp32 -> fp16 stream convert (4 elems / thread)
__global__ void convert_kernel(const float* __restrict__ src, __half* __restrict__ dst,
                               long n4) {
    long i = (long)blockIdx.x * blockDim.x + threadIdx.x;
    if (i < n4) {
        float4 v = *reinterpret_cast<const float4*>(src + i * 4);
        __half2 h0 = __floats2half2_rn(v.x, v.y);
        __half2 h1 = __floats2half2_rn(v.z, v.w);
        uint2 packed = make_uint2(*reinterpret_cast<uint32_t*>(&h0),
                                  *reinterpret_cast<uint32_t*>(&h1));
        *reinterpret_cast<uint2*>(dst + i * 4) = packed;
    }
}

// g_W1TH[n][k] = fp16(W1[k][n]);  W1: [1536, 768] row-major
__global__ void transpose_kernel(const float* __restrict__ W1) {
    __shared__ float t[32][33];
    int n0 = blockIdx.x * 32, k0 = blockIdx.y * 32;
    int tx = threadIdx.x, ty = threadIdx.y;
#pragma unroll
    for (int i = 0; i < 4; ++i)
        t[ty + 8 * i][tx] = W1[(size_t)(k0 + ty + 8 * i) * HID + n0 + tx];
    __syncthreads();
#pragma unroll
    for (int i = 0; i < 4; ++i)
        g_W1TH[(size_t)(n0 + ty + 8 * i) * W1ROWS + k0 + tx] = __float2half_rn(t[tx][ty + 8 * i]);
}

// ---------------- fp16 GEMM, BM=128 x BN=256, warp tile 64x64 ----------------
// MAIN=false: g_Mpart = A @ W1T[:, 0:768]^T + b1
// MAIN=true : fused cand GEMM + Mpart gather + relu + W2 dot + scatter atomicAdd
template <bool MAIN>
__global__ __launch_bounds__(256, 1)
void gemm_kernel(const __half* __restrict__ A, int kOff,
                 const float* __restrict__ b1, const float* __restrict__ W2,
                 const float* __restrict__ b2v,
                 const int* __restrict__ midx, const int* __restrict__ cidx,
                 float* __restrict__ out) {
    extern __shared__ __half smem[];

    const int tid   = threadIdx.x;
    const int warp  = tid >> 5;
    const int lane  = tid & 31;
    const int warpM = warp >> 2;          // 0..1  (64 rows)
    const int warpN = warp & 3;           // 0..3  (64 cols)
    const int gid   = lane >> 2;          // 0..7
    const int tg    = lane & 3;           // 0..3

    const __half* Ablk = A + (size_t)blockIdx.y * BM * HID;
    const __half* Bblk = g_W1TH + (size_t)blockIdx.x * BN * W1ROWS + kOff;

    float c[4][8][4];
#pragma unroll
    for (int mi = 0; mi < 4; ++mi)
#pragma unroll
        for (int ni = 0; ni < 8; ++ni)
#pragma unroll
            for (int j = 0; j < 4; ++j) c[mi][ni][j] = 0.f;

    auto load_tiles = [&](int kt, int stage) {
        __half* sa = smem + stage * STAGE_H;
        __half* sb = sa + A_STAGE_H;
#pragma unroll
        for (int i = 0; i < 2; ++i) {                 // A: 128 rows x 32 halves (4 cp/row)
            int idx = tid + i * 256;
            int r = idx >> 2, cc = idx & 3;
            cp_async16(sa + r * SROW + cc * 8, Ablk + (size_t)r * HID + kt * BK + cc * 8);
        }
#pragma unroll
        for (int i = 0; i < 4; ++i) {                 // B: 256 rows x 32 halves
            int idx = tid + i * 256;
            int n = idx >> 2, cc = idx & 3;
            cp_async16(sb + n * SROW + cc * 8, Bblk + (size_t)n * W1ROWS + kt * BK + cc * 8);
        }
    };

    load_tiles(0, 0); cp_commit();
    load_tiles(1, 1); cp_commit();

    int stage = 0;
    for (int kt = 0; kt < NKT; ++kt) {
        if (kt + 1 < NKT) cp_wait<1>(); else cp_wait<0>();
        __syncthreads();
        if (kt + 2 < NKT) {
            int ws = stage + 2; if (ws >= NSTAGE) ws -= NSTAGE;
            load_tiles(kt + 2, ws);
            cp_commit();
        }

        const __half2* sa2 = reinterpret_cast<const __half2*>(smem + stage * STAGE_H);
        const __half2* sb2 = reinterpret_cast<const __half2*>(smem + stage * STAGE_H + A_STAGE_H);
        const int S2 = SROW / 2;   // 20 half2 per row

#pragma unroll
        for (int ks = 0; ks < 2; ++ks) {              // two k16 steps per k-tile
            const int kh = ks * 8;                    // half2 column offset
            uint32_t a[4][4], b[8][2];
#pragma unroll
            for (int mi = 0; mi < 4; ++mi) {
                const int r = warpM * 64 + mi * 16 + gid;
                a[mi][0] = *reinterpret_cast<const uint32_t*>(&sa2[r * S2 + kh + tg]);
                a[mi][1] = *reinterpret_cast<const uint32_t*>(&sa2[(r + 8) * S2 + kh + tg]);
                a[mi][2] = *reinterpret_cast<const uint32_t*>(&sa2[r * S2 + kh + tg + 4]);
                a[mi][3] = *reinterpret_cast<const uint32_t*>(&sa2[(r + 8) * S2 + kh + tg + 4]);
            }
#pragma unroll
            for (int ni = 0; ni < 8; ++ni) {
                const int col = warpN * 64 + ni * 8 + gid;
                b[ni][0] = *reinterpret_cast<const uint32_t*>(&sb2[col * S2 + kh + tg]);
                b[ni][1] = *reinterpret_cast<const uint32_t*>(&sb2[col * S2 + kh + tg + 4]);
            }
#pragma unroll
            for (int mi = 0; mi < 4; ++mi)
#pragma unroll
                for (int ni = 0; ni < 8; ++ni)
                    mma_f16(c[mi][ni][0], c[mi][ni][1], c[mi][ni][2], c[mi][ni][3],
                            a[mi][0], a[mi][1], a[mi][2], a[mi][3],
                            b[ni][0], b[ni][1]);
        }
        __syncthreads();
        ++stage; if (stage >= NSTAGE) stage = 0;
    }

    const int rowBase = blockIdx.y * BM + warpM * 64;
    const int colBase = blockIdx.x * BN + warpN * 64;

    if (MAIN) {
        float w2v[8][2];
#pragma unroll
        for (int ni = 0; ni < 8; ++ni) {
            w2v[ni][0] = __ldg(W2 + colBase + ni * 8 + tg * 2);
            w2v[ni][1] = __ldg(W2 + colBase + ni * 8 + tg * 2 + 1);
        }
#pragma unroll
        for (int mi = 0; mi < 4; ++mi)
#pragma unroll
            for (int rr = 0; rr < 2; ++rr) {
                const int prow = rowBase + mi * 16 + rr * 8 + gid;
                const int m = __ldg(midx + prow);
                const float* mp = g_Mpart + (size_t)m * HID;
                float acc = 0.f;
#pragma unroll
                for (int ni = 0; ni < 8; ++ni) {
                    const int col = colBase + ni * 8 + tg * 2;
                    float v0 = c[mi][ni][rr * 2]     + __ldg(mp + col);
                    float v1 = c[mi][ni][rr * 2 + 1] + __ldg(mp + col + 1);
                    acc = fmaf(fmaxf(v0, 0.f), w2v[ni][0], acc);
                    acc = fmaf(fmaxf(v1, 0.f), w2v[ni][1], acc);
                }
                acc += __shfl_xor_sync(0xffffffffu, acc, 1);
                acc += __shfl_xor_sync(0xffffffffu, acc, 2);
                if (tg == 0) {
                    if (blockIdx.x == 0 && warpN == 0) acc += __ldg(b2v);
                    atomicAdd(out + (size_t)m * (MAXK + 1) + __ldg(cidx + prow), acc);
                }
            }
    } else {
#pragma unroll
        for (int mi = 0; mi < 4; ++mi)
#pragma unroll
            for (int rr = 0; rr < 2; ++rr) {
                const int row = rowBase + mi * 16 + rr * 8 + gid;
#pragma unroll
                for (int ni = 0; ni < 8; ++ni) {
                    const int col = colBase + ni * 8 + tg * 2;
                    float2 v;
                    v.x = c[mi][ni][rr * 2]     + __ldg(b1 + col);
                    v.y = c[mi][ni][rr * 2 + 1] + __ldg(b1 + col + 1);
                    *reinterpret_cast<float2*>(&g_Mpart[(size_t)row * HID + col]) = v;
                }
            }
    }
}

// ---------------- launch ----------------
extern "C" void kernel_launch(void* const* d_in, const int* in_sizes, int n_in,
                              void* d_out, int out_size) {
    const float* mention = (const float*)d_in[0];  // [4096, 768]
    const float* cand    = (const float*)d_in[1];  // [131072, 768]
    const float* W1      = (const float*)d_in[2];  // [1536, 768]
    const float* b1      = (const float*)d_in[3];  // [768]
    const float* W2      = (const float*)d_in[4];  // [768, 1]
    const float* b2      = (const float*)d_in[5];  // [1]
    const float* prior   = (const float*)d_in[6];  // [4096, 64]
    const float* nota    = (const float*)d_in[7];  // []
    const int*   midx    = (const int*)d_in[8];    // [T]
    const int*   cidx    = (const int*)d_in[9];    // [T]
    float* out = (float*)d_out;                    // [4096, 65]

    const int N = in_sizes[0] / HID;   // 4096
    const int T = in_sizes[1] / HID;   // 131072

    __half* candH; cudaGetSymbolAddress((void**)&candH, g_candH);
    __half* mentH; cudaGetSymbolAddress((void**)&mentH, g_mentH);

    cudaFuncSetAttribute(gemm_kernel<false>, cudaFuncAttributeMaxDynamicSharedMemorySize, SMEM_BYTES);
    cudaFuncSetAttribute(gemm_kernel<true>,  cudaFuncAttributeMaxDynamicSharedMemorySize, SMEM_BYTES);

    // 1) out = 0.5*prior (+ nota col)
    init_out_kernel<<<(N * (MAXK + 1) + 255) / 256, 256>>>(out, prior, nota, N);

    // 2) fp16 conversions
    long cand4 = (long)T * HID / 4;
    convert_kernel<<<(int)((cand4 + 255) / 256), 256>>>(cand, candH, cand4);
    long ment4 = (long)N * HID / 4;
    convert_kernel<<<(int)((ment4 + 255) / 256), 256>>>(mention, mentH, ment4);
    transpose_kernel<<<dim3(HID / 32, W1ROWS / 32), dim3(32, 8)>>>(W1);

    // 3) Mpart = mention @ W1_top + b1
    gemm_kernel<false><<<dim3(HID / BN, N / BM), 256, SMEM_BYTES>>>(
        mentH, 0, b1, W2, b2, nullptr, nullptr, out);

    // 4) fused: cand @ W1_bot -> +Mpart -> relu -> @W2 (+b2) -> scatter-add
    gemm_kernel<true><<<dim3(HID / BN, T / BM), 256, SMEM_BYTES>>>(
        candH, HID, b1, W2, b2, midx, cidx, out);
}

// round 5
// speedup vs baseline: 1.4843x; 1.1168x over previous
#include <cuda_runtime.h>
#include <cuda_fp16.h>
#include <cstdint>

// ---------------- problem constants ----------------
#define HID 768
#define W1ROWS 1536
#define MAXK 64
#define NMENT 4096

// ---------------- tiling ----------------
#define BM 128
#define BN 256
#define BK 32                         // 32 k-values per tile (2 mma k16 steps)
#define NKT (HID / BK)                // 24
#define SROWA 40                      // A smem stride in floats  (LDS.64: 4g+t mod16 injective)
#define SROWB 40                      // B smem stride in halves  (LDS.32: 20g+t mod32 injective)
#define A_STAGE_F (BM * SROWA)        // 5120 floats  = 20480 B
#define B_STAGE_H (BN * SROWB)        // 10240 halves = 20480 B
#define STAGE_BYTES (A_STAGE_F * 4 + B_STAGE_H * 2)   // 40960
#define NSTAGE 3
#define SMEM_BYTES (NSTAGE * STAGE_BYTES)             // 122880 B

// ---------------- device scratch (static, no allocs) ----------------
__device__ float  g_Mpart[NMENT * HID];     // mention @ W1_top + b1 (fp32)
__device__ __half g_W1TH[HID * W1ROWS];     // W1 transposed -> [n][k] fp16

// ---------------- helpers ----------------
__device__ __forceinline__ void cp_async16(void* sptr, const void* gptr) {
    uint32_t s = (uint32_t)__cvta_generic_to_shared(sptr);
    asm volatile("cp.async.cg.shared.global [%0], [%1], 16;\n" :: "r"(s), "l"(gptr));
}
__device__ __forceinline__ void cp_commit() { asm volatile("cp.async.commit_group;\n"); }
template <int W_>
__device__ __forceinline__ void cp_wait() { asm volatile("cp.async.wait_group %0;\n" :: "n"(W_)); }

__device__ __forceinline__ void mma_f16(float& c0, float& c1, float& c2, float& c3,
                                        uint32_t a0, uint32_t a1, uint32_t a2, uint32_t a3,
                                        uint32_t b0, uint32_t b1) {
    asm volatile(
        "mma.sync.aligned.m16n8k16.row.col.f32.f16.f16.f32 "
        "{%0,%1,%2,%3}, {%4,%5,%6,%7}, {%8,%9}, {%0,%1,%2,%3};\n"
        : "+f"(c0), "+f"(c1), "+f"(c2), "+f"(c3)
        : "r"(a0), "r"(a1), "r"(a2), "r"(a3), "r"(b0), "r"(b1));
}

__device__ __forceinline__ uint32_t f2_to_h2(float2 v) {
    __half2 h = __floats2half2_rn(v.x, v.y);          // single cvt.rn.f16x2.f32
    return *reinterpret_cast<uint32_t*>(&h);
}

// ---------------- aux kernels ----------------
__global__ void init_out_kernel(float* __restrict__ out, const float* __restrict__ prior,
                                const float* __restrict__ nota, int n) {
    int i = blockIdx.x * blockDim.x + threadIdx.x;
    if (i < n * (MAXK + 1)) {
        int k = i % (MAXK + 1);
        int row = i / (MAXK + 1);
        out[i] = (k < MAXK) ? 0.5f * prior[row * MAXK + k] : nota[0];
    }
}

// g_W1TH[n][k] = fp16(W1[k][n]);  W1: [1536, 768] row-major
__global__ void transpose_kernel(const float* __restrict__ W1) {
    __shared__ float t[32][33];
    int n0 = blockIdx.x * 32, k0 = blockIdx.y * 32;
    int tx = threadIdx.x, ty = threadIdx.y;
#pragma unroll
    for (int i = 0; i < 4; ++i)
        t[ty + 8 * i][tx] = W1[(size_t)(k0 + ty + 8 * i) * HID + n0 + tx];
    __syncthreads();
#pragma unroll
    for (int i = 0; i < 4; ++i)
        g_W1TH[(size_t)(n0 + ty + 8 * i) * W1ROWS + k0 + tx] = __float2half_rn(t[tx][ty + 8 * i]);
}

// ---------------- fp16-MMA GEMM with fp32 A loads ----------------
// A is fp32 [rows, 768]; B is g_W1TH fp16; warp tile 64x64 (mi=4, ni=8).
// MAIN=false: g_Mpart = A @ W1T[:, kOff..]^T + b1
// MAIN=true : fused cand GEMM + Mpart gather + relu + W2 dot + scatter atomicAdd
template <bool MAIN>
__global__ __launch_bounds__(256, 1)
void gemm_kernel(const float* __restrict__ A, int kOff,
                 const float* __restrict__ b1, const float* __restrict__ W2,
                 const float* __restrict__ b2v,
                 const int* __restrict__ midx, const int* __restrict__ cidx,
                 float* __restrict__ out) {
    extern __shared__ char smem[];

    const int tid   = threadIdx.x;
    const int warp  = tid >> 5;
    const int lane  = tid & 31;
    const int warpM = warp >> 2;          // 0..1  (64 rows)
    const int warpN = warp & 3;           // 0..3  (64 cols)
    const int gid   = lane >> 2;          // 0..7
    const int tg    = lane & 3;           // 0..3

    const float*  Ablk = A + (size_t)blockIdx.y * BM * HID;
    const __half* Bblk = g_W1TH + (size_t)blockIdx.x * BN * W1ROWS + kOff;

    float c[4][8][4];
#pragma unroll
    for (int mi = 0; mi < 4; ++mi)
#pragma unroll
        for (int ni = 0; ni < 8; ++ni)
#pragma unroll
            for (int j = 0; j < 4; ++j) c[mi][ni][j] = 0.f;

    auto load_tiles = [&](int kt, int stage) {
        float*  sa = reinterpret_cast<float*>(smem + stage * STAGE_BYTES);
        __half* sb = reinterpret_cast<__half*>(smem + stage * STAGE_BYTES + A_STAGE_F * 4);
#pragma unroll
        for (int i = 0; i < 4; ++i) {                 // A: 128 rows x 32 floats (8x16B/row)
            int idx = tid + i * 256;
            int r = idx >> 3, cc = idx & 7;
            cp_async16(sa + r * SROWA + cc * 4, Ablk + (size_t)r * HID + kt * BK + cc * 4);
        }
#pragma unroll
        for (int i = 0; i < 4; ++i) {                 // B: 256 rows x 32 halves (4x16B/row)
            int idx = tid + i * 256;
            int n = idx >> 2, cc = idx & 3;
            cp_async16(sb + n * SROWB + cc * 8, Bblk + (size_t)n * W1ROWS + kt * BK + cc * 8);
        }
    };

    load_tiles(0, 0); cp_commit();
    load_tiles(1, 1); cp_commit();

    int stage = 0;
    for (int kt = 0; kt < NKT; ++kt) {
        if (kt + 1 < NKT) cp_wait<1>(); else cp_wait<0>();
        __syncthreads();
        if (kt + 2 < NKT) {
            int ws = stage + 2; if (ws >= NSTAGE) ws -= NSTAGE;
            load_tiles(kt + 2, ws);
            cp_commit();
        }

        const float*  sa  = reinterpret_cast<const float*>(smem + stage * STAGE_BYTES);
        const __half2* sb2 = reinterpret_cast<const __half2*>(smem + stage * STAGE_BYTES + A_STAGE_F * 4);
        const int S2 = SROWB / 2;   // 20 half2 per B row

#pragma unroll
        for (int ks = 0; ks < 2; ++ks) {              // two k16 steps per k-tile
            const int kf = ks * 16;                   // float/half column offset
            const int kh = ks * 8;                    // half2 column offset
            uint32_t a[4][4], b[8][2];
#pragma unroll
            for (int mi = 0; mi < 4; ++mi) {
                const int r = warpM * 64 + mi * 16 + gid;
                a[mi][0] = f2_to_h2(*reinterpret_cast<const float2*>(&sa[r * SROWA + kf + 2 * tg]));
                a[mi][1] = f2_to_h2(*reinterpret_cast<const float2*>(&sa[(r + 8) * SROWA + kf + 2 * tg]));
                a[mi][2] = f2_to_h2(*reinterpret_cast<const float2*>(&sa[r * SROWA + kf + 8 + 2 * tg]));
                a[mi][3] = f2_to_h2(*reinterpret_cast<const float2*>(&sa[(r + 8) * SROWA + kf + 8 + 2 * tg]));
            }
#pragma unroll
            for (int ni = 0; ni < 8; ++ni) {
                const int col = warpN * 64 + ni * 8 + gid;
                b[ni][0] = *reinterpret_cast<const uint32_t*>(&sb2[col * S2 + kh + tg]);
                b[ni][1] = *reinterpret_cast<const uint32_t*>(&sb2[col * S2 + kh + tg + 4]);
            }
#pragma unroll
            for (int mi = 0; mi < 4; ++mi)
#pragma unroll
                for (int ni = 0; ni < 8; ++ni)
                    mma_f16(c[mi][ni][0], c[mi][ni][1], c[mi][ni][2], c[mi][ni][3],
                            a[mi][0], a[mi][1], a[mi][2], a[mi][3],
                            b[ni][0], b[ni][1]);
        }
        ++stage; if (stage >= NSTAGE) stage = 0;
    }

    const int rowBase = blockIdx.y * BM + warpM * 64;
    const int colBase = blockIdx.x * BN + warpN * 64;

    if (MAIN) {
        float w2v[8][2];
#pragma unroll
        for (int ni = 0; ni < 8; ++ni) {
            w2v[ni][0] = __ldg(W2 + colBase + ni * 8 + tg * 2);
            w2v[ni][1] = __ldg(W2 + colBase + ni * 8 + tg * 2 + 1);
        }
#pragma unroll
        for (int mi = 0; mi < 4; ++mi)
#pragma unroll
            for (int rr = 0; rr < 2; ++rr) {
                const int prow = rowBase + mi * 16 + rr * 8 + gid;
                const int m = __ldg(midx + prow);
                const float* mp = g_Mpart + (size_t)m * HID;
                float acc = 0.f;
#pragma unroll
                for (int ni = 0; ni < 8; ++ni) {
                    const int col = colBase + ni * 8 + tg * 2;
                    float v0 = c[mi][ni][rr * 2]     + __ldg(mp + col);
                    float v1 = c[mi][ni][rr * 2 + 1] + __ldg(mp + col + 1);
                    acc = fmaf(fmaxf(v0, 0.f), w2v[ni][0], acc);
                    acc = fmaf(fmaxf(v1, 0.f), w2v[ni][1], acc);
                }
                acc += __shfl_xor_sync(0xffffffffu, acc, 1);
                acc += __shfl_xor_sync(0xffffffffu, acc, 2);
                if (tg == 0) {
                    if (blockIdx.x == 0 && warpN == 0) acc += __ldg(b2v);
                    atomicAdd(out + (size_t)m * (MAXK + 1) + __ldg(cidx + prow), acc);
                }
            }
    } else {
#pragma unroll
        for (int mi = 0; mi < 4; ++mi)
#pragma unroll
            for (int rr = 0; rr < 2; ++rr) {
                const int row = rowBase + mi * 16 + rr * 8 + gid;
#pragma unroll
                for (int ni = 0; ni < 8; ++ni) {
                    const int col = colBase + ni * 8 + tg * 2;
                    float2 v;
                    v.x = c[mi][ni][rr * 2]     + __ldg(b1 + col);
                    v.y = c[mi][ni][rr * 2 + 1] + __ldg(b1 + col + 1);
                    *reinterpret_cast<float2*>(&g_Mpart[(size_t)row * HID + col]) = v;
                }
            }
    }
}

// ---------------- launch ----------------
extern "C" void kernel_launch(void* const* d_in, const int* in_sizes, int n_in,
                              void* d_out, int out_size) {
    const float* mention = (const float*)d_in[0];  // [4096, 768]
    const float* cand    = (const float*)d_in[1];  // [131072, 768]
    const float* W1      = (const float*)d_in[2];  // [1536, 768]
    const float* b1      = (const float*)d_in[3];  // [768]
    const float* W2      = (const float*)d_in[4];  // [768, 1]
    const float* b2      = (const float*)d_in[5];  // [1]
    const float* prior   = (const float*)d_in[6];  // [4096, 64]
    const float* nota    = (const float*)d_in[7];  // []
    const int*   midx    = (const int*)d_in[8];    // [T]
    const int*   cidx    = (const int*)d_in[9];    // [T]
    float* out = (float*)d_out;                    // [4096, 65]

    const int N = in_sizes[0] / HID;   // 4096
    const int T = in_sizes[1] / HID;   // 131072

    cudaFuncSetAttribute(gemm_kernel<false>, cudaFuncAttributeMaxDynamicSharedMemorySize, SMEM_BYTES);
    cudaFuncSetAttribute(gemm_kernel<true>,  cudaFuncAttributeMaxDynamicSharedMemorySize, SMEM_BYTES);

    // 0) out = 0.5*prior (+ nota col)
    init_out_kernel<<<(N * (MAXK + 1) + 255) / 256, 256>>>(out, prior, nota, N);

    // 1) W1T (fp16) = W1^T
    transpose_kernel<<<dim3(HID / 32, W1ROWS / 32), dim3(32, 8)>>>(W1);

    // 2) Mpart = mention @ W1_top + b1
    gemm_kernel<false><<<dim3(HID / BN, N / BM), 256, SMEM_BYTES>>>(
        mention, 0, b1, W2, b2, nullptr, nullptr, out);

    // 3) fused: cand @ W1_bot -> +Mpart -> relu -> @W2 (+b2) -> scatter-add
    gemm_kernel<true><<<dim3(HID / BN, T / BM), 256, SMEM_BYTES>>>(
        cand, HID, b1, W2, b2, midx, cidx, out);
}